// round 2
// baseline (speedup 1.0000x reference)
#include <cuda_runtime.h>
#include <cstdint>

#define NA 200000
#define NW 50000
#define D 256
#define P 64
#define E_TIC 4000000
#define E_REL 1000000

typedef unsigned long long u64;

// ---------------- scratch (device globals: no allocation allowed) ----------
__device__ float g_h_tic[(size_t)NA * P];   // x_ac @ W_neigh_tic   (51.2 MB)
__device__ float g_h_rel[(size_t)NA * P];   // x_ac @ W_neigh_rel   (51.2 MB)
__device__ float g_acc_tic[(size_t)NA * P]; // segment sums (tic)   (51.2 MB)
__device__ float g_acc_rel[(size_t)NW * P]; // segment sums (rel)   (12.8 MB)
__device__ float g_deg_tic[NA];
__device__ float g_deg_rel[NW];

// ---------------- f32x2 helpers (sm_103a packed fp32) ----------------------
__device__ __forceinline__ u64 pack2(float lo, float hi) {
    u64 r; asm("mov.b64 %0, {%1, %2};" : "=l"(r) : "f"(lo), "f"(hi)); return r;
}
__device__ __forceinline__ void unpack2(u64 v, float& lo, float& hi) {
    asm("mov.b64 {%0, %1}, %2;" : "=f"(lo), "=f"(hi) : "l"(v));
}
__device__ __forceinline__ void fma2(u64& acc, u64 a, u64 b) {
    asm("fma.rn.f32x2 %0, %1, %2, %0;" : "+l"(acc) : "l"(a), "l"(b));
}

// ---------------- zero accumulators ----------------------------------------
__global__ __launch_bounds__(256) void zero_kernel() {
    int i = blockIdx.x * blockDim.x + threadIdx.x;
    int stride = gridDim.x * blockDim.x;
    float4 z = make_float4(0.f, 0.f, 0.f, 0.f);
    float4* a0 = reinterpret_cast<float4*>(g_acc_tic);
    float4* a1 = reinterpret_cast<float4*>(g_acc_rel);
    float4* d0 = reinterpret_cast<float4*>(g_deg_tic);
    float4* d1 = reinterpret_cast<float4*>(g_deg_rel);
    for (int j = i; j < NA * P / 4; j += stride) a0[j] = z;
    for (int j = i; j < NW * P / 4; j += stride) a1[j] = z;
    for (int j = i; j < NA / 4; j += stride) d0[j] = z;
    for (int j = i; j < NW / 4; j += stride) d1[j] = z;
}

// ---------------- GEMM 1: g_h = x_ac @ [W_neigh_tic | W_neigh_rel] ---------
// BM=64, BN=128, BK=32, 256 threads, each computes 8 rows x 4 cols via
// f32x2 row-pairs. A tile stored transposed [k][row] so LDS.64 yields packed
// row pairs directly.
__global__ __launch_bounds__(256) void gemm_neigh(const float* __restrict__ x,
                                                  const float* __restrict__ Wtic,
                                                  const float* __restrict__ Wrel) {
    __shared__ __align__(16) float A_s[32][66];
    __shared__ __align__(16) float W_s[32][128];
    int tid = threadIdx.x;
    int tx = tid & 31, ty = tid >> 5;
    int row0 = blockIdx.x * 64;

    u64 acc[4][4];
#pragma unroll
    for (int i = 0; i < 4; i++)
#pragma unroll
        for (int c = 0; c < 4; c++) acc[i][c] = 0ull;

    for (int k0 = 0; k0 < D; k0 += 32) {
        // A tile: 64 rows x 32 k, transposed into A_s[k][row]
#pragma unroll
        for (int t = 0; t < 2; t++) {
            int s = tid + t * 256;        // 0..511 float4 slots
            int r = s >> 3, kc = s & 7;
            float4 v = *(const float4*)&x[(size_t)(row0 + r) * D + k0 + kc * 4];
            A_s[kc * 4 + 0][r] = v.x;
            A_s[kc * 4 + 1][r] = v.y;
            A_s[kc * 4 + 2][r] = v.z;
            A_s[kc * 4 + 3][r] = v.w;
        }
        // W tile: 32 k x 128 cols (tic cols 0-63, rel cols 64-127)
#pragma unroll
        for (int t = 0; t < 4; t++) {
            int s = tid + t * 256;        // 0..1023 float4 slots
            int kk = s >> 5, c4 = s & 31;
            float4 v;
            if (c4 < 16) v = *(const float4*)&Wtic[(k0 + kk) * P + c4 * 4];
            else         v = *(const float4*)&Wrel[(k0 + kk) * P + (c4 - 16) * 4];
            *(float4*)&W_s[kk][c4 * 4] = v;
        }
        __syncthreads();
#pragma unroll
        for (int k = 0; k < 32; k++) {
            u64 a[4];
#pragma unroll
            for (int i = 0; i < 4; i++)
                a[i] = *(const u64*)&A_s[k][ty * 8 + 2 * i];
            float4 w = *(const float4*)&W_s[k][tx * 4];
            u64 wp[4] = {pack2(w.x, w.x), pack2(w.y, w.y),
                         pack2(w.z, w.z), pack2(w.w, w.w)};
#pragma unroll
            for (int i = 0; i < 4; i++)
#pragma unroll
                for (int c = 0; c < 4; c++) fma2(acc[i][c], a[i], wp[c]);
        }
        __syncthreads();
    }

    int col = tx * 4;
    float* dstb = (col < P) ? g_h_tic : g_h_rel;
    int cc = col & (P - 1);
#pragma unroll
    for (int i = 0; i < 4; i++) {
        float lo[4], hi[4];
#pragma unroll
        for (int c = 0; c < 4; c++) unpack2(acc[i][c], lo[c], hi[c]);
        int r0 = row0 + ty * 8 + 2 * i;
        *(float4*)&dstb[(size_t)r0 * P + cc]       = make_float4(lo[0], lo[1], lo[2], lo[3]);
        *(float4*)&dstb[(size_t)(r0 + 1) * P + cc] = make_float4(hi[0], hi[1], hi[2], hi[3]);
    }
}

// ---------------- edge scatter: weighted messages + degree -----------------
// 16 threads per edge; each handles one float4 of the 64-wide message.
template <int REL>
__global__ __launch_bounds__(256) void scatter_edges(const int* __restrict__ src,
                                                     const int* __restrict__ dst,
                                                     const float* __restrict__ we,
                                                     int E) {
    int gtid = blockIdx.x * blockDim.x + threadIdx.x;
    int e = gtid >> 4;
    int q = gtid & 15;
    if (e >= E) return;
    int s = __ldg(&src[e]);
    int d = __ldg(&dst[e]);
    float w = __ldg(&we[e]);
    const float* h = REL ? g_h_rel : g_h_tic;
    float*     acc = REL ? g_acc_rel : g_acc_tic;
    float*     deg = REL ? g_deg_rel : g_deg_tic;
    float4 hv = *(const float4*)&h[(size_t)s * P + q * 4];
    float mx = hv.x * w, my = hv.y * w, mz = hv.z * w, mw = hv.w * w;
    float* p = &acc[(size_t)d * P + q * 4];
    asm volatile("red.global.add.v4.f32 [%0], {%1, %2, %3, %4};"
                 :: "l"(p), "f"(mx), "f"(my), "f"(mz), "f"(mw) : "memory");
    if (q == 0) {
        asm volatile("red.global.add.f32 [%0], %1;"
                     :: "l"(&deg[d]), "f"(1.0f) : "memory");
    }
}

// ---------------- fused output GEMM + SAGE epilogue ------------------------
// MODE 0: out = x_ac @ W_self_tic + acc_tic/deg + b          (h_ac)
// MODE 1: out = 0.5*(x_w[:, :64] + x_w @ W_self_rel + acc_rel/deg + b)  (h_w)
template <int MODE>
__global__ __launch_bounds__(256) void gemm_out(const float* __restrict__ x,
                                                const float* __restrict__ Wself,
                                                const float* __restrict__ b,
                                                float* __restrict__ out,
                                                int nrows) {
    __shared__ __align__(16) float A_s[32][66];
    __shared__ __align__(16) float W_s[32][64];
    int tid = threadIdx.x;
    int tx = tid & 31, ty = tid >> 5;
    int row0 = blockIdx.x * 64;

    const float* accb = MODE ? g_acc_rel : g_acc_tic;
    const float* degb = MODE ? g_deg_rel : g_deg_tic;

    u64 acc[4][2];
#pragma unroll
    for (int i = 0; i < 4; i++) { acc[i][0] = 0ull; acc[i][1] = 0ull; }

    for (int k0 = 0; k0 < D; k0 += 32) {
#pragma unroll
        for (int t = 0; t < 2; t++) {
            int s = tid + t * 256;
            int r = s >> 3, kc = s & 7;
            float4 v = make_float4(0.f, 0.f, 0.f, 0.f);
            if (row0 + r < nrows)
                v = *(const float4*)&x[(size_t)(row0 + r) * D + k0 + kc * 4];
            A_s[kc * 4 + 0][r] = v.x;
            A_s[kc * 4 + 1][r] = v.y;
            A_s[kc * 4 + 2][r] = v.z;
            A_s[kc * 4 + 3][r] = v.w;
        }
#pragma unroll
        for (int t = 0; t < 2; t++) {
            int s = tid + t * 256;        // 0..511 float4 slots over [32][64]
            int kk = s >> 4, c4 = s & 15;
            float4 v = *(const float4*)&Wself[(k0 + kk) * P + c4 * 4];
            *(float4*)&W_s[kk][c4 * 4] = v;
        }
        __syncthreads();
#pragma unroll
        for (int k = 0; k < 32; k++) {
            u64 a[4];
#pragma unroll
            for (int i = 0; i < 4; i++)
                a[i] = *(const u64*)&A_s[k][ty * 8 + 2 * i];
            float2 w = *(const float2*)&W_s[k][tx * 2];
            u64 wp0 = pack2(w.x, w.x);
            u64 wp1 = pack2(w.y, w.y);
#pragma unroll
            for (int i = 0; i < 4; i++) {
                fma2(acc[i][0], a[i], wp0);
                fma2(acc[i][1], a[i], wp1);
            }
        }
        __syncthreads();
    }

    int c0 = tx * 2;
    float2 bb = *(const float2*)&b[c0];
#pragma unroll
    for (int i = 0; i < 4; i++) {
        float lo0, hi0, lo1, hi1;
        unpack2(acc[i][0], lo0, hi0);
        unpack2(acc[i][1], lo1, hi1);
        int r0 = row0 + ty * 8 + 2 * i;
#pragma unroll
        for (int half = 0; half < 2; half++) {
            int r = r0 + half;
            if (r >= nrows) continue;
            float g0 = half ? hi0 : lo0;
            float g1 = half ? hi1 : lo1;
            float dg = degb[r];
            float inv = dg > 0.f ? 1.0f / dg : 0.0f;
            float2 nb = *(const float2*)&accb[(size_t)r * P + c0];
            float v0 = g0 + bb.x + nb.x * inv;
            float v1 = g1 + bb.y + nb.y * inv;
            if (MODE) {
                v0 = 0.5f * (x[(size_t)r * D + c0]     + v0);
                v1 = 0.5f * (x[(size_t)r * D + c0 + 1] + v1);
            }
            float2 o; o.x = v0; o.y = v1;
            *(float2*)&out[(size_t)r * P + c0] = o;
        }
    }
}

// ---------------- launch ----------------------------------------------------
extern "C" void kernel_launch(void* const* d_in, const int* in_sizes, int n_in,
                              void* d_out, int out_size) {
    const float* x_ac        = (const float*)d_in[0];
    const float* x_w         = (const float*)d_in[1];
    const int*   src_tic     = (const int*)d_in[2];
    const int*   dst_tic     = (const int*)d_in[3];
    const float* w_tic       = (const float*)d_in[4];
    const int*   src_rel     = (const int*)d_in[5];
    const int*   dst_rel     = (const int*)d_in[6];
    const float* w_rel       = (const float*)d_in[7];
    const float* W_self_tic  = (const float*)d_in[8];
    const float* W_neigh_tic = (const float*)d_in[9];
    const float* b_tic       = (const float*)d_in[10];
    const float* W_self_rel  = (const float*)d_in[11];
    const float* W_neigh_rel = (const float*)d_in[12];
    const float* b_rel       = (const float*)d_in[13];
    float* out = (float*)d_out;

    zero_kernel<<<2048, 256>>>();
    gemm_neigh<<<NA / 64, 256>>>(x_ac, W_neigh_tic, W_neigh_rel);
    scatter_edges<0><<<(E_TIC * 16) / 256, 256>>>(src_tic, dst_tic, w_tic, E_TIC);
    scatter_edges<1><<<(E_REL * 16) / 256, 256>>>(src_rel, dst_rel, w_rel, E_REL);
    gemm_out<0><<<NA / 64, 256>>>(x_ac, W_self_tic, b_tic, out, NA);
    gemm_out<1><<<(NW + 63) / 64, 256>>>(x_w, W_self_rel, b_rel, out + (size_t)NA * P, NW);
}

// round 4
// speedup vs baseline: 1.1272x; 1.1272x over previous
#include <cuda_runtime.h>
#include <cstdint>

#define NA 200000
#define NW 50000
#define D 256
#define P 64
#define E_TIC 4000000
#define E_REL 1000000

typedef unsigned long long u64;

// ---------------- scratch (device globals: no allocation allowed) ----------
__device__ float g_h_tic[(size_t)NA * P];   // x_ac @ W_neigh_tic   (51.2 MB)
__device__ float g_h_rel[(size_t)NA * P];   // x_ac @ W_neigh_rel   (51.2 MB)
__device__ float g_acc_tic[(size_t)NA * P]; // segment sums (tic)   (51.2 MB)
__device__ float g_acc_rel[(size_t)NW * P]; // segment sums (rel)   (12.8 MB)
__device__ float g_deg_tic[NA];
__device__ float g_deg_rel[NW];

// ---------------- f32x2 helpers (sm_103a packed fp32) ----------------------
__device__ __forceinline__ u64 pack2(float lo, float hi) {
    u64 r; asm("mov.b64 %0, {%1, %2};" : "=l"(r) : "f"(lo), "f"(hi)); return r;
}
__device__ __forceinline__ void unpack2(u64 v, float& lo, float& hi) {
    asm("mov.b64 {%0, %1}, %2;" : "=f"(lo), "=f"(hi) : "l"(v));
}
__device__ __forceinline__ void fma2(u64& acc, u64 a, u64 b) {
    asm("fma.rn.f32x2 %0, %1, %2, %0;" : "+l"(acc) : "l"(a), "l"(b));
}

// ---------------- zero accumulators ----------------------------------------
__global__ __launch_bounds__(256) void zero_kernel() {
    int i = blockIdx.x * blockDim.x + threadIdx.x;
    int stride = gridDim.x * blockDim.x;
    float4 z = make_float4(0.f, 0.f, 0.f, 0.f);
    float4* a0 = reinterpret_cast<float4*>(g_acc_tic);
    float4* a1 = reinterpret_cast<float4*>(g_acc_rel);
    float4* d0 = reinterpret_cast<float4*>(g_deg_tic);
    float4* d1 = reinterpret_cast<float4*>(g_deg_rel);
    for (int j = i; j < NA * P / 4; j += stride) a0[j] = z;
    for (int j = i; j < NW * P / 4; j += stride) a1[j] = z;
    for (int j = i; j < NA / 4; j += stride) d0[j] = z;
    for (int j = i; j < NW / 4; j += stride) d1[j] = z;
}

// ---------------- GEMM 1: g_h = x_ac @ [W_neigh_tic | W_neigh_rel] ---------
// BM=64, BN=128, BK=32, 256 threads, each computes 8 rows x 4 cols via
// f32x2 row-pairs. A tile stored transposed [k][row] so LDS.64 yields packed
// row pairs directly.
__global__ __launch_bounds__(256) void gemm_neigh(const float* __restrict__ x,
                                                  const float* __restrict__ Wtic,
                                                  const float* __restrict__ Wrel) {
    __shared__ __align__(16) float A_s[32][66];
    __shared__ __align__(16) float W_s[32][128];
    int tid = threadIdx.x;
    int tx = tid & 31, ty = tid >> 5;
    int row0 = blockIdx.x * 64;

    u64 acc[4][4];
#pragma unroll
    for (int i = 0; i < 4; i++)
#pragma unroll
        for (int c = 0; c < 4; c++) acc[i][c] = 0ull;

    for (int k0 = 0; k0 < D; k0 += 32) {
        // A tile: 64 rows x 32 k, transposed into A_s[k][row]
#pragma unroll
        for (int t = 0; t < 2; t++) {
            int s = tid + t * 256;        // 0..511 float4 slots
            int r = s >> 3, kc = s & 7;
            float4 v = *(const float4*)&x[(size_t)(row0 + r) * D + k0 + kc * 4];
            A_s[kc * 4 + 0][r] = v.x;
            A_s[kc * 4 + 1][r] = v.y;
            A_s[kc * 4 + 2][r] = v.z;
            A_s[kc * 4 + 3][r] = v.w;
        }
        // W tile: 32 k x 128 cols (tic cols 0-63, rel cols 64-127)
#pragma unroll
        for (int t = 0; t < 4; t++) {
            int s = tid + t * 256;        // 0..1023 float4 slots
            int kk = s >> 5, c4 = s & 31;
            float4 v;
            if (c4 < 16) v = *(const float4*)&Wtic[(k0 + kk) * P + c4 * 4];
            else         v = *(const float4*)&Wrel[(k0 + kk) * P + (c4 - 16) * 4];
            *(float4*)&W_s[kk][c4 * 4] = v;
        }
        __syncthreads();
#pragma unroll
        for (int k = 0; k < 32; k++) {
            u64 a[4];
#pragma unroll
            for (int i = 0; i < 4; i++)
                a[i] = *(const u64*)&A_s[k][ty * 8 + 2 * i];
            float4 w = *(const float4*)&W_s[k][tx * 4];
            u64 wp[4] = {pack2(w.x, w.x), pack2(w.y, w.y),
                         pack2(w.z, w.z), pack2(w.w, w.w)};
#pragma unroll
            for (int i = 0; i < 4; i++)
#pragma unroll
                for (int c = 0; c < 4; c++) fma2(acc[i][c], a[i], wp[c]);
        }
        __syncthreads();
    }

    int col = tx * 4;
    float* dstb = (col < P) ? g_h_tic : g_h_rel;
    int cc = col & (P - 1);
#pragma unroll
    for (int i = 0; i < 4; i++) {
        float lo[4], hi[4];
#pragma unroll
        for (int c = 0; c < 4; c++) unpack2(acc[i][c], lo[c], hi[c]);
        int r0 = row0 + ty * 8 + 2 * i;
        *(float4*)&dstb[(size_t)r0 * P + cc]       = make_float4(lo[0], lo[1], lo[2], lo[3]);
        *(float4*)&dstb[(size_t)(r0 + 1) * P + cc] = make_float4(hi[0], hi[1], hi[2], hi[3]);
    }
}

// ---------------- edge scatter: weighted messages + degree -----------------
// 8 threads per edge; each handles TWO float4 slices (contiguous 128B halves)
// -> 2 independent gathers + 2 independent red.v4 per thread (MLP up),
// and index loads shared across 8 lanes instead of 16.
template <int REL>
__global__ __launch_bounds__(256) void scatter_edges(const int* __restrict__ src,
                                                     const int* __restrict__ dst,
                                                     const float* __restrict__ we,
                                                     int E) {
    int gtid = blockIdx.x * blockDim.x + threadIdx.x;
    int e = gtid >> 3;
    int q = gtid & 7;
    if (e >= E) return;
    int s = __ldg(&src[e]);
    int d = __ldg(&dst[e]);
    float w = __ldg(&we[e]);
    const float* h = REL ? g_h_rel : g_h_tic;
    float*     acc = REL ? g_acc_rel : g_acc_tic;
    float*     deg = REL ? g_deg_rel : g_deg_tic;
    const float4* hp = (const float4*)&h[(size_t)s * P];
    // two independent gathers (floats [q*4, q*4+4) and [32+q*4, 32+q*4+4))
    float4 v0 = __ldg(&hp[q]);
    float4 v1 = __ldg(&hp[q + 8]);
    float4* a0 = (float4*)&acc[(size_t)d * P + q * 4];
    float4* a1 = a0 + 8;
    asm volatile("red.global.add.v4.f32 [%0], {%1, %2, %3, %4};"
                 :: "l"(a0), "f"(v0.x * w), "f"(v0.y * w), "f"(v0.z * w), "f"(v0.w * w)
                 : "memory");
    asm volatile("red.global.add.v4.f32 [%0], {%1, %2, %3, %4};"
                 :: "l"(a1), "f"(v1.x * w), "f"(v1.y * w), "f"(v1.z * w), "f"(v1.w * w)
                 : "memory");
    if (q == 0) {
        asm volatile("red.global.add.f32 [%0], %1;"
                     :: "l"(&deg[d]), "f"(1.0f) : "memory");
    }
}

// ---------------- fused output GEMM + SAGE epilogue ------------------------
// MODE 0: out = x_ac @ W_self_tic + acc_tic/deg + b          (h_ac)
// MODE 1: out = 0.5*(x_w[:, :64] + x_w @ W_self_rel + acc_rel/deg + b)  (h_w)
template <int MODE>
__global__ __launch_bounds__(256) void gemm_out(const float* __restrict__ x,
                                                const float* __restrict__ Wself,
                                                const float* __restrict__ b,
                                                float* __restrict__ out,
                                                int nrows) {
    __shared__ __align__(16) float A_s[32][66];
    __shared__ __align__(16) float W_s[32][64];
    int tid = threadIdx.x;
    int tx = tid & 31, ty = tid >> 5;
    int row0 = blockIdx.x * 64;

    const float* accb = MODE ? g_acc_rel : g_acc_tic;
    const float* degb = MODE ? g_deg_rel : g_deg_tic;

    u64 acc[4][2];
#pragma unroll
    for (int i = 0; i < 4; i++) { acc[i][0] = 0ull; acc[i][1] = 0ull; }

    for (int k0 = 0; k0 < D; k0 += 32) {
#pragma unroll
        for (int t = 0; t < 2; t++) {
            int s = tid + t * 256;
            int r = s >> 3, kc = s & 7;
            float4 v = make_float4(0.f, 0.f, 0.f, 0.f);
            if (row0 + r < nrows)
                v = *(const float4*)&x[(size_t)(row0 + r) * D + k0 + kc * 4];
            A_s[kc * 4 + 0][r] = v.x;
            A_s[kc * 4 + 1][r] = v.y;
            A_s[kc * 4 + 2][r] = v.z;
            A_s[kc * 4 + 3][r] = v.w;
        }
#pragma unroll
        for (int t = 0; t < 2; t++) {
            int s = tid + t * 256;        // 0..511 float4 slots over [32][64]
            int kk = s >> 4, c4 = s & 15;
            float4 v = *(const float4*)&Wself[(k0 + kk) * P + c4 * 4];
            *(float4*)&W_s[kk][c4 * 4] = v;
        }
        __syncthreads();
#pragma unroll
        for (int k = 0; k < 32; k++) {
            u64 a[4];
#pragma unroll
            for (int i = 0; i < 4; i++)
                a[i] = *(const u64*)&A_s[k][ty * 8 + 2 * i];
            float2 w = *(const float2*)&W_s[k][tx * 2];
            u64 wp0 = pack2(w.x, w.x);
            u64 wp1 = pack2(w.y, w.y);
#pragma unroll
            for (int i = 0; i < 4; i++) {
                fma2(acc[i][0], a[i], wp0);
                fma2(acc[i][1], a[i], wp1);
            }
        }
        __syncthreads();
    }

    int c0 = tx * 2;
    float2 bb = *(const float2*)&b[c0];
#pragma unroll
    for (int i = 0; i < 4; i++) {
        float lo0, hi0, lo1, hi1;
        unpack2(acc[i][0], lo0, hi0);
        unpack2(acc[i][1], lo1, hi1);
        int r0 = row0 + ty * 8 + 2 * i;
#pragma unroll
        for (int half = 0; half < 2; half++) {
            int r = r0 + half;
            if (r >= nrows) continue;
            float g0 = half ? hi0 : lo0;
            float g1 = half ? hi1 : lo1;
            float dg = degb[r];
            float inv = dg > 0.f ? 1.0f / dg : 0.0f;
            float2 nb = *(const float2*)&accb[(size_t)r * P + c0];
            float v0 = g0 + bb.x + nb.x * inv;
            float v1 = g1 + bb.y + nb.y * inv;
            if (MODE) {
                v0 = 0.5f * (x[(size_t)r * D + c0]     + v0);
                v1 = 0.5f * (x[(size_t)r * D + c0 + 1] + v1);
            }
            float2 o; o.x = v0; o.y = v1;
            *(float2*)&out[(size_t)r * P + c0] = o;
        }
    }
}

// ---------------- launch: fork-join two-stream DAG --------------------------
//  s0 (capture/default): gemm_neigh -> scatter<0> -> gemm_out<0>
//  s1:                   zero       -> scatter<1> -> gemm_out<1>
//  zero overlaps the fma-bound gemm_neigh; the small rel chain (~90us) hides
//  entirely under the tic chain (~380us).
extern "C" void kernel_launch(void* const* d_in, const int* in_sizes, int n_in,
                              void* d_out, int out_size) {
    const float* x_ac        = (const float*)d_in[0];
    const float* x_w         = (const float*)d_in[1];
    const int*   src_tic     = (const int*)d_in[2];
    const int*   dst_tic     = (const int*)d_in[3];
    const float* w_tic       = (const float*)d_in[4];
    const int*   src_rel     = (const int*)d_in[5];
    const int*   dst_rel     = (const int*)d_in[6];
    const float* w_rel       = (const float*)d_in[7];
    const float* W_self_tic  = (const float*)d_in[8];
    const float* W_neigh_tic = (const float*)d_in[9];
    const float* b_tic       = (const float*)d_in[10];
    const float* W_self_rel  = (const float*)d_in[11];
    const float* W_neigh_rel = (const float*)d_in[12];
    const float* b_rel       = (const float*)d_in[13];
    float* out = (float*)d_out;

    static cudaStream_t s1 = nullptr;
    static cudaEvent_t ev0 = nullptr, evZ = nullptr, evN = nullptr, evD = nullptr;
    if (s1 == nullptr) {
        cudaStreamCreateWithFlags(&s1, cudaStreamNonBlocking);
        cudaEventCreateWithFlags(&ev0, cudaEventDisableTiming);
        cudaEventCreateWithFlags(&evZ, cudaEventDisableTiming);
        cudaEventCreateWithFlags(&evN, cudaEventDisableTiming);
        cudaEventCreateWithFlags(&evD, cudaEventDisableTiming);
    }

    // fork: s1 joins the capture via event from the origin stream
    cudaEventRecord(ev0, 0);
    cudaStreamWaitEvent(s1, ev0, 0);

    zero_kernel<<<2048, 256, 0, s1>>>();                       // s1
    gemm_neigh<<<NA / 64, 256>>>(x_ac, W_neigh_tic, W_neigh_rel); // s0

    cudaEventRecord(evN, 0);    // gemm_neigh done
    cudaEventRecord(evZ, s1);   // zero done
    cudaStreamWaitEvent(s1, evN, 0);  // scatter<1> needs h_rel
    cudaStreamWaitEvent(0, evZ, 0);   // scatter<0> needs zeroed acc/deg

    scatter_edges<0><<<(E_TIC * 8 + 255) / 256, 256>>>(src_tic, dst_tic, w_tic, E_TIC);          // s0
    scatter_edges<1><<<(E_REL * 8 + 255) / 256, 256, 0, s1>>>(src_rel, dst_rel, w_rel, E_REL);   // s1

    gemm_out<0><<<NA / 64, 256>>>(x_ac, W_self_tic, b_tic, out, NA);                              // s0
    gemm_out<1><<<(NW + 63) / 64, 256, 0, s1>>>(x_w, W_self_rel, b_rel, out + (size_t)NA * P, NW);// s1

    // join
    cudaEventRecord(evD, s1);
    cudaStreamWaitEvent(0, evD, 0);
}

// round 6
// speedup vs baseline: 1.4760x; 1.3095x over previous
#include <cuda_runtime.h>
#include <cstdint>

#define NA 200000
#define NW 50000
#define D 256
#define P 64
#define E_TIC 4000000
#define E_REL 1000000

typedef unsigned long long u64;
typedef unsigned int u32;

// ---------------- scratch (device globals: no allocation allowed) ----------
__device__ float g_h_tic[(size_t)NA * P];   // x_ac @ W_neigh_tic   (51.2 MB)
__device__ float g_h_rel[(size_t)NA * P];   // x_ac @ W_neigh_rel   (51.2 MB)
__device__ float g_acc_tic[(size_t)NA * P]; // segment sums (tic)   (51.2 MB)
__device__ float g_acc_rel[(size_t)NW * P]; // segment sums (rel)   (12.8 MB)
__device__ float g_deg_tic[NA];
__device__ float g_deg_rel[NW];

// ---------------- helpers ---------------------------------------------------
__device__ __forceinline__ u32 f2tf32(float f) {
    u32 o; asm("cvt.rna.tf32.f32 %0, %1;" : "=r"(o) : "f"(f)); return o;
}

__device__ __forceinline__ void mma_tf32(float* c, const u32* a, const u32* b) {
    asm volatile(
        "mma.sync.aligned.m16n8k8.row.col.f32.tf32.tf32.f32 "
        "{%0,%1,%2,%3}, {%4,%5,%6,%7}, {%8,%9}, {%0,%1,%2,%3};"
        : "+f"(c[0]), "+f"(c[1]), "+f"(c[2]), "+f"(c[3])
        : "r"(a[0]), "r"(a[1]), "r"(a[2]), "r"(a[3]), "r"(b[0]), "r"(b[1]));
}

// ---------------- zero accumulators ----------------------------------------
__global__ __launch_bounds__(256) void zero_kernel() {
    int i = blockIdx.x * blockDim.x + threadIdx.x;
    int stride = gridDim.x * blockDim.x;
    float4 z = make_float4(0.f, 0.f, 0.f, 0.f);
    float4* a0 = reinterpret_cast<float4*>(g_acc_tic);
    float4* a1 = reinterpret_cast<float4*>(g_acc_rel);
    float4* d0 = reinterpret_cast<float4*>(g_deg_tic);
    float4* d1 = reinterpret_cast<float4*>(g_deg_rel);
    for (int j = i; j < NA * P / 4; j += stride) a0[j] = z;
    for (int j = i; j < NW * P / 4; j += stride) a1[j] = z;
    for (int j = i; j < NA / 4; j += stride) d0[j] = z;
    for (int j = i; j < NW / 4; j += stride) d1[j] = z;
}

// ---------------- tf32 mma.sync GEMM ---------------------------------------
// BM=128, BN=N_TILE, BK=32, 256 threads (8 warps), warp grid WM x WN.
// MODE 0: N=128, D = x_ac @ [W_neigh_tic | W_neigh_rel] -> g_h_tic/g_h_rel
// MODE 1: N=64,  out = x @ W_self + b + acc_tic/deg
// MODE 2: N=64,  out = 0.5*(x[:, :64] + x @ W_self + b + acc_rel/deg)
// smem stride 36 floats: fragment LDS banks (4m+k)%32 -> conflict-free.
template <int N_TILE, int MODE, int WM, int WN>
__global__ __launch_bounds__(256) void gemm_mma(const float* __restrict__ x,
                                                const float* __restrict__ W0,
                                                const float* __restrict__ W1,
                                                const float* __restrict__ b,
                                                float* __restrict__ out,
                                                int nrows) {
    constexpr int WTM = 128 / WM;       // warp tile M
    constexpr int WTN = N_TILE / WN;    // warp tile N
    constexpr int MT = WTM / 16;        // m16 tiles per warp
    constexpr int NT = WTN / 8;         // n8 tiles per warp

    __shared__ u32 A_s[128][36];
    __shared__ u32 B_s[N_TILE][36];
    __shared__ float b_s[P];

    int tid = threadIdx.x;
    int wid = tid >> 5, lid = tid & 31;
    int g = lid >> 2, t4 = lid & 3;
    int wm = wid / WN, wn = wid % WN;
    int m_warp = wm * WTM, n_warp = wn * WTN;
    int row0 = blockIdx.x * 128;

    if (MODE != 0 && tid < P) b_s[tid] = b[tid];

    float acc[MT][NT][4];
#pragma unroll
    for (int i = 0; i < MT; i++)
#pragma unroll
        for (int j = 0; j < NT; j++)
#pragma unroll
            for (int v = 0; v < 4; v++) acc[i][j][v] = 0.f;

    for (int c = 0; c < 8; c++) {
        int k0 = c * 32;
        if (c > 0) __syncthreads();
        // A: 128 rows x 32 k, tf32-converted, padded stride 36
#pragma unroll
        for (int it = 0; it < 4; it++) {
            int idx = tid + it * 256;          // 0..1023
            int m = idx >> 3, q = idx & 7;
            float4 v = make_float4(0.f, 0.f, 0.f, 0.f);
            if (row0 + m < nrows)
                v = *(const float4*)&x[(size_t)(row0 + m) * D + k0 + q * 4];
            uint4 t;
            t.x = f2tf32(v.x); t.y = f2tf32(v.y);
            t.z = f2tf32(v.z); t.w = f2tf32(v.w);
            *(uint4*)&A_s[m][q * 4] = t;
        }
        // B: W chunk transposed -> B_s[n][k]
#pragma unroll
        for (int it = 0; it < N_TILE * 32 / 256; it++) {
            int i = tid + it * 256;
            int k = i / N_TILE, n = i % N_TILE;
            float w;
            if (MODE == 0)
                w = (n < P) ? W0[(k0 + k) * P + n] : W1[(k0 + k) * P + (n - P)];
            else
                w = W0[(k0 + k) * P + n];
            B_s[n][k] = f2tf32(w);
        }
        __syncthreads();
#pragma unroll
        for (int ks = 0; ks < 4; ks++) {
            int kk = ks * 8;
            u32 afr[MT][4];
#pragma unroll
            for (int mt = 0; mt < MT; mt++) {
                int m = m_warp + mt * 16 + g;
                afr[mt][0] = A_s[m][kk + t4];
                afr[mt][1] = A_s[m + 8][kk + t4];
                afr[mt][2] = A_s[m][kk + t4 + 4];
                afr[mt][3] = A_s[m + 8][kk + t4 + 4];
            }
            u32 bfr[NT][2];
#pragma unroll
            for (int nt = 0; nt < NT; nt++) {
                int n = n_warp + nt * 8 + g;
                bfr[nt][0] = B_s[n][kk + t4];
                bfr[nt][1] = B_s[n][kk + t4 + 4];
            }
#pragma unroll
            for (int mt = 0; mt < MT; mt++)
#pragma unroll
                for (int nt = 0; nt < NT; nt++)
                    mma_tf32(acc[mt][nt], afr[mt], bfr[nt]);
        }
    }

    // ---------------- epilogue ----------------
    if (MODE != 0) __syncthreads();  // b_s visible (also written pre-loop; cheap)

#pragma unroll
    for (int mt = 0; mt < MT; mt++) {
#pragma unroll
        for (int half = 0; half < 2; half++) {
            int r = row0 + m_warp + mt * 16 + g + half * 8;
            if (r >= nrows) continue;
            float inv = 0.f;
            const float* accb = nullptr;
            if (MODE != 0) {
                float dg = (MODE == 1) ? g_deg_tic[r] : g_deg_rel[r];
                inv = dg > 0.f ? 1.0f / dg : 0.0f;
                accb = (MODE == 1) ? g_acc_tic : g_acc_rel;
            }
#pragma unroll
            for (int nt = 0; nt < NT; nt++) {
                int col = n_warp + nt * 8 + t4 * 2;
                float v0 = acc[mt][nt][half * 2 + 0];
                float v1 = acc[mt][nt][half * 2 + 1];
                if (MODE == 0) {
                    float* dstb = (col < P) ? g_h_tic : g_h_rel;
                    int cc = col & (P - 1);
                    float2 o; o.x = v0; o.y = v1;
                    *(float2*)&dstb[(size_t)r * P + cc] = o;
                } else {
                    float2 av = *(const float2*)&accb[(size_t)r * P + col];
                    v0 += b_s[col]     + av.x * inv;
                    v1 += b_s[col + 1] + av.y * inv;
                    if (MODE == 2) {
                        float2 xv = *(const float2*)&x[(size_t)r * D + col];
                        v0 = 0.5f * (xv.x + v0);
                        v1 = 0.5f * (xv.y + v1);
                    }
                    float2 o; o.x = v0; o.y = v1;
                    *(float2*)&out[(size_t)r * P + col] = o;
                }
            }
        }
    }
}

// ---------------- edge scatter: weighted messages + degree -----------------
template <int REL>
__global__ __launch_bounds__(256) void scatter_edges(const int* __restrict__ src,
                                                     const int* __restrict__ dst,
                                                     const float* __restrict__ we,
                                                     int E) {
    int gtid = blockIdx.x * blockDim.x + threadIdx.x;
    int e = gtid >> 3;
    int q = gtid & 7;
    if (e >= E) return;
    int s = __ldg(&src[e]);
    int d = __ldg(&dst[e]);
    float w = __ldg(&we[e]);
    const float* h = REL ? g_h_rel : g_h_tic;
    float*     acc = REL ? g_acc_rel : g_acc_tic;
    float*     deg = REL ? g_deg_rel : g_deg_tic;
    const float4* hp = (const float4*)&h[(size_t)s * P];
    float4 v0 = __ldg(&hp[q]);
    float4 v1 = __ldg(&hp[q + 8]);
    float4* a0 = (float4*)&acc[(size_t)d * P + q * 4];
    float4* a1 = a0 + 8;
    asm volatile("red.global.add.v4.f32 [%0], {%1, %2, %3, %4};"
                 :: "l"(a0), "f"(v0.x * w), "f"(v0.y * w), "f"(v0.z * w), "f"(v0.w * w)
                 : "memory");
    asm volatile("red.global.add.v4.f32 [%0], {%1, %2, %3, %4};"
                 :: "l"(a1), "f"(v1.x * w), "f"(v1.y * w), "f"(v1.z * w), "f"(v1.w * w)
                 : "memory");
    if (q == 0) {
        asm volatile("red.global.add.f32 [%0], %1;"
                     :: "l"(&deg[d]), "f"(1.0f) : "memory");
    }
}

// ---------------- launch: fork-join two-stream DAG --------------------------
extern "C" void kernel_launch(void* const* d_in, const int* in_sizes, int n_in,
                              void* d_out, int out_size) {
    const float* x_ac        = (const float*)d_in[0];
    const float* x_w         = (const float*)d_in[1];
    const int*   src_tic     = (const int*)d_in[2];
    const int*   dst_tic     = (const int*)d_in[3];
    const float* w_tic       = (const float*)d_in[4];
    const int*   src_rel     = (const int*)d_in[5];
    const int*   dst_rel     = (const int*)d_in[6];
    const float* w_rel       = (const float*)d_in[7];
    const float* W_self_tic  = (const float*)d_in[8];
    const float* W_neigh_tic = (const float*)d_in[9];
    const float* b_tic       = (const float*)d_in[10];
    const float* W_self_rel  = (const float*)d_in[11];
    const float* W_neigh_rel = (const float*)d_in[12];
    const float* b_rel       = (const float*)d_in[13];
    float* out = (float*)d_out;

    static cudaStream_t s1 = nullptr;
    static cudaEvent_t ev0 = nullptr, evZ = nullptr, evN = nullptr, evD = nullptr;
    if (s1 == nullptr) {
        cudaStreamCreateWithFlags(&s1, cudaStreamNonBlocking);
        cudaEventCreateWithFlags(&ev0, cudaEventDisableTiming);
        cudaEventCreateWithFlags(&evZ, cudaEventDisableTiming);
        cudaEventCreateWithFlags(&evN, cudaEventDisableTiming);
        cudaEventCreateWithFlags(&evD, cudaEventDisableTiming);
    }

    const int GRID_A = (NA + 127) / 128;   // 1563
    const int GRID_W = (NW + 127) / 128;   // 391

    // fork
    cudaEventRecord(ev0, 0);
    cudaStreamWaitEvent(s1, ev0, 0);

    zero_kernel<<<2048, 256, 0, s1>>>();                                   // s1
    gemm_mma<128, 0, 2, 4><<<GRID_A, 256>>>(x_ac, W_neigh_tic, W_neigh_rel,
                                            nullptr, nullptr, NA);         // s0

    cudaEventRecord(evN, 0);    // h ready
    cudaEventRecord(evZ, s1);   // zero done
    cudaStreamWaitEvent(s1, evN, 0);
    cudaStreamWaitEvent(0, evZ, 0);

    scatter_edges<0><<<(E_TIC * 8 + 255) / 256, 256>>>(src_tic, dst_tic, w_tic, E_TIC);
    scatter_edges<1><<<(E_REL * 8 + 255) / 256, 256, 0, s1>>>(src_rel, dst_rel, w_rel, E_REL);

    gemm_mma<64, 1, 4, 2><<<GRID_A, 256>>>(x_ac, W_self_tic, nullptr,
                                           b_tic, out, NA);                // s0
    gemm_mma<64, 2, 4, 2><<<GRID_W, 256, 0, s1>>>(x_w, W_self_rel, nullptr,
                                                  b_rel, out + (size_t)NA * P, NW);

    // join
    cudaEventRecord(evD, s1);
    cudaStreamWaitEvent(0, evD, 0);
}

// round 7
// speedup vs baseline: 1.6221x; 1.0990x over previous
#include <cuda_runtime.h>
#include <cstdint>

#define NA 200000
#define NW 50000
#define D 256
#define P 64
#define E_TIC 4000000
#define E_REL 1000000

#define NB_TIC ((NA + 2047) / 2048)   // 98
#define NB_REL ((NW + 2047) / 2048)   // 25

typedef unsigned long long u64;
typedef unsigned int u32;

// ---------------- scratch (device globals: no allocation allowed) ----------
__device__ float g_h_tic[(size_t)NA * P];   // x_ac @ W_neigh_tic
__device__ float g_h_rel[(size_t)NA * P];   // x_ac @ W_neigh_rel
__device__ float g_acc_tic[(size_t)NA * P]; // mean-aggregated neigh (tic)
__device__ float g_acc_rel[(size_t)NW * P]; // mean-aggregated neigh (rel)

__device__ int  g_cnt_tic[NA];
__device__ int  g_cnt_rel[NW];
__device__ int  g_start_tic[NA];
__device__ int  g_start_rel[NW];
__device__ int  g_pos_tic[NA];
__device__ int  g_pos_rel[NW];
__device__ int  g_bsum_tic[128];
__device__ int  g_bsum_rel[128];
__device__ u64  g_csr_tic[E_TIC];           // packed (w<<32 | src)
__device__ u64  g_csr_rel[E_REL];

// ---------------- helpers ---------------------------------------------------
__device__ __forceinline__ u32 f2tf32(float f) {
    u32 o; asm("cvt.rna.tf32.f32 %0, %1;" : "=r"(o) : "f"(f)); return o;
}

__device__ __forceinline__ void mma_tf32(float* c, const u32* a, const u32* b) {
    asm volatile(
        "mma.sync.aligned.m16n8k8.row.col.f32.tf32.tf32.f32 "
        "{%0,%1,%2,%3}, {%4,%5,%6,%7}, {%8,%9}, {%0,%1,%2,%3};"
        : "+f"(c[0]), "+f"(c[1]), "+f"(c[2]), "+f"(c[3])
        : "r"(a[0]), "r"(a[1]), "r"(a[2]), "r"(a[3]), "r"(b[0]), "r"(b[1]));
}

// ---------------- CSR build --------------------------------------------------
__global__ __launch_bounds__(256) void zero_cnt() {
    int i = blockIdx.x * blockDim.x + threadIdx.x;
    if (i < NA) g_cnt_tic[i] = 0;
    if (i < NW) g_cnt_rel[i] = 0;
}

template <int REL>
__global__ __launch_bounds__(256) void hist(const int* __restrict__ dst, int E) {
    int e = blockIdx.x * blockDim.x + threadIdx.x;
    if (e >= E) return;
    int d = __ldg(&dst[e]);
    int* cnt = REL ? g_cnt_rel : g_cnt_tic;
    atomicAdd(&cnt[d], 1);
}

template <int REL>
__global__ __launch_bounds__(256) void scan1() {
    const int N = REL ? NW : NA;
    const int* cnt = REL ? g_cnt_rel : g_cnt_tic;
    int* start = REL ? g_start_rel : g_start_tic;
    int* bsum = REL ? g_bsum_rel : g_bsum_tic;

    __shared__ int sh[256];
    int t = threadIdx.x;
    int base = blockIdx.x * 2048 + t * 8;
    int v[8]; int s = 0;
#pragma unroll
    for (int j = 0; j < 8; j++) {
        int idx = base + j;
        int c = (idx < N) ? cnt[idx] : 0;
        v[j] = s; s += c;
    }
    sh[t] = s;
    __syncthreads();
    int own = s;
    for (int off = 1; off < 256; off <<= 1) {
        int y = (t >= off) ? sh[t - off] : 0;
        __syncthreads();
        sh[t] += y;
        __syncthreads();
    }
    int texcl = sh[t] - own;
#pragma unroll
    for (int j = 0; j < 8; j++) {
        int idx = base + j;
        if (idx < N) start[idx] = v[j] + texcl;
    }
    if (t == 255) bsum[blockIdx.x] = sh[255];
}

template <int REL>
__global__ __launch_bounds__(128) void scan2() {
    const int NB = REL ? NB_REL : NB_TIC;
    int* bsum = REL ? g_bsum_rel : g_bsum_tic;
    __shared__ int sh[128];
    int t = threadIdx.x;
    int val = (t < NB) ? bsum[t] : 0;
    sh[t] = val;
    __syncthreads();
    for (int off = 1; off < 128; off <<= 1) {
        int y = (t >= off) ? sh[t - off] : 0;
        __syncthreads();
        sh[t] += y;
        __syncthreads();
    }
    if (t < NB) bsum[t] = sh[t] - val;
}

template <int REL>
__global__ __launch_bounds__(256) void scan3() {
    const int N = REL ? NW : NA;
    int* start = REL ? g_start_rel : g_start_tic;
    int* pos = REL ? g_pos_rel : g_pos_tic;
    const int* bsum = REL ? g_bsum_rel : g_bsum_tic;
    int add = bsum[blockIdx.x];
    int base = blockIdx.x * 2048 + threadIdx.x * 8;
#pragma unroll
    for (int j = 0; j < 8; j++) {
        int idx = base + j;
        if (idx < N) {
            int v = start[idx] + add;
            start[idx] = v;
            pos[idx] = v;
        }
    }
}

template <int REL>
__global__ __launch_bounds__(256) void reorder(const int* __restrict__ src,
                                               const int* __restrict__ dst,
                                               const float* __restrict__ we,
                                               int E) {
    int e = blockIdx.x * blockDim.x + threadIdx.x;
    if (e >= E) return;
    int d = __ldg(&dst[e]);
    int s = __ldg(&src[e]);
    float w = __ldg(&we[e]);
    int* pos = REL ? g_pos_rel : g_pos_tic;
    u64* csr = REL ? g_csr_rel : g_csr_tic;
    int p = atomicAdd(&pos[d], 1);
    csr[p] = ((u64)__float_as_uint(w) << 32) | (u32)s;
}

// ---------------- gather: warp per dst row, mean aggregation ---------------
template <int REL>
__global__ __launch_bounds__(256) void gather_rows() {
    const int N = REL ? NW : NA;
    const int* start = REL ? g_start_rel : g_start_tic;
    const int* cnt = REL ? g_cnt_rel : g_cnt_tic;
    const u64* csr = REL ? g_csr_rel : g_csr_tic;
    const float* h = REL ? g_h_rel : g_h_tic;
    float* acc = REL ? g_acc_rel : g_acc_tic;

    int r = blockIdx.x * 8 + (threadIdx.x >> 5);
    int lid = threadIdx.x & 31;
    if (r >= N) return;
    int beg = start[r];
    int c = cnt[r];
    int end = beg + c;

    float ax = 0.f, ay = 0.f;
    int i = beg;
    for (; i + 4 <= end; i += 4) {
        u64 p0 = __ldg(&csr[i]);
        u64 p1 = __ldg(&csr[i + 1]);
        u64 p2 = __ldg(&csr[i + 2]);
        u64 p3 = __ldg(&csr[i + 3]);
        float2 h0 = *(const float2*)&h[(size_t)(u32)p0 * P + lid * 2];
        float2 h1 = *(const float2*)&h[(size_t)(u32)p1 * P + lid * 2];
        float2 h2 = *(const float2*)&h[(size_t)(u32)p2 * P + lid * 2];
        float2 h3 = *(const float2*)&h[(size_t)(u32)p3 * P + lid * 2];
        float w0 = __uint_as_float((u32)(p0 >> 32));
        float w1 = __uint_as_float((u32)(p1 >> 32));
        float w2 = __uint_as_float((u32)(p2 >> 32));
        float w3 = __uint_as_float((u32)(p3 >> 32));
        ax += h0.x * w0 + h1.x * w1 + h2.x * w2 + h3.x * w3;
        ay += h0.y * w0 + h1.y * w1 + h2.y * w2 + h3.y * w3;
    }
    for (; i < end; i++) {
        u64 p = __ldg(&csr[i]);
        float2 hv = *(const float2*)&h[(size_t)(u32)p * P + lid * 2];
        float w = __uint_as_float((u32)(p >> 32));
        ax += hv.x * w;
        ay += hv.y * w;
    }
    float inv = (c > 0) ? 1.0f / (float)c : 0.0f;
    float2 o; o.x = ax * inv; o.y = ay * inv;
    *(float2*)&acc[(size_t)r * P + lid * 2] = o;
}

// ---------------- tf32 mma.sync GEMM ---------------------------------------
// MODE 0: N=128, -> g_h_tic | g_h_rel
// MODE 1: N=64,  out = x @ W_self + b + acc_tic (mean already)
// MODE 2: N=64,  out = 0.5*(x[:, :64] + x @ W_self + b + acc_rel)
template <int N_TILE, int MODE, int WM, int WN>
__global__ __launch_bounds__(256) void gemm_mma(const float* __restrict__ x,
                                                const float* __restrict__ W0,
                                                const float* __restrict__ W1,
                                                const float* __restrict__ b,
                                                float* __restrict__ out,
                                                int nrows) {
    constexpr int WTM = 128 / WM;
    constexpr int WTN = N_TILE / WN;
    constexpr int MT = WTM / 16;
    constexpr int NT = WTN / 8;

    __shared__ u32 A_s[128][36];
    __shared__ u32 B_s[N_TILE][36];
    __shared__ float b_s[P];

    int tid = threadIdx.x;
    int wid = tid >> 5, lid = tid & 31;
    int g = lid >> 2, t4 = lid & 3;
    int wm = wid / WN, wn = wid % WN;
    int m_warp = wm * WTM, n_warp = wn * WTN;
    int row0 = blockIdx.x * 128;

    if (MODE != 0 && tid < P) b_s[tid] = b[tid];

    float acc[MT][NT][4];
#pragma unroll
    for (int i = 0; i < MT; i++)
#pragma unroll
        for (int j = 0; j < NT; j++)
#pragma unroll
            for (int v = 0; v < 4; v++) acc[i][j][v] = 0.f;

    for (int c = 0; c < 8; c++) {
        int k0 = c * 32;
        if (c > 0) __syncthreads();
#pragma unroll
        for (int it = 0; it < 4; it++) {
            int idx = tid + it * 256;
            int m = idx >> 3, q = idx & 7;
            float4 v = make_float4(0.f, 0.f, 0.f, 0.f);
            if (row0 + m < nrows)
                v = *(const float4*)&x[(size_t)(row0 + m) * D + k0 + q * 4];
            uint4 t;
            t.x = f2tf32(v.x); t.y = f2tf32(v.y);
            t.z = f2tf32(v.z); t.w = f2tf32(v.w);
            *(uint4*)&A_s[m][q * 4] = t;
        }
#pragma unroll
        for (int it = 0; it < N_TILE * 32 / 256; it++) {
            int i = tid + it * 256;
            int k = i / N_TILE, n = i % N_TILE;
            float w;
            if (MODE == 0)
                w = (n < P) ? W0[(k0 + k) * P + n] : W1[(k0 + k) * P + (n - P)];
            else
                w = W0[(k0 + k) * P + n];
            B_s[n][k] = f2tf32(w);
        }
        __syncthreads();
#pragma unroll
        for (int ks = 0; ks < 4; ks++) {
            int kk = ks * 8;
            u32 afr[MT][4];
#pragma unroll
            for (int mt = 0; mt < MT; mt++) {
                int m = m_warp + mt * 16 + g;
                afr[mt][0] = A_s[m][kk + t4];
                afr[mt][1] = A_s[m + 8][kk + t4];
                afr[mt][2] = A_s[m][kk + t4 + 4];
                afr[mt][3] = A_s[m + 8][kk + t4 + 4];
            }
            u32 bfr[NT][2];
#pragma unroll
            for (int nt = 0; nt < NT; nt++) {
                int n = n_warp + nt * 8 + g;
                bfr[nt][0] = B_s[n][kk + t4];
                bfr[nt][1] = B_s[n][kk + t4 + 4];
            }
#pragma unroll
            for (int mt = 0; mt < MT; mt++)
#pragma unroll
                for (int nt = 0; nt < NT; nt++)
                    mma_tf32(acc[mt][nt], afr[mt], bfr[nt]);
        }
    }

    if (MODE != 0) __syncthreads();

#pragma unroll
    for (int mt = 0; mt < MT; mt++) {
#pragma unroll
        for (int half = 0; half < 2; half++) {
            int r = row0 + m_warp + mt * 16 + g + half * 8;
            if (r >= nrows) continue;
            const float* accb = (MODE == 1) ? g_acc_tic :
                                (MODE == 2) ? g_acc_rel : nullptr;
#pragma unroll
            for (int nt = 0; nt < NT; nt++) {
                int col = n_warp + nt * 8 + t4 * 2;
                float v0 = acc[mt][nt][half * 2 + 0];
                float v1 = acc[mt][nt][half * 2 + 1];
                if (MODE == 0) {
                    float* dstb = (col < P) ? g_h_tic : g_h_rel;
                    int cc = col & (P - 1);
                    float2 o; o.x = v0; o.y = v1;
                    *(float2*)&dstb[(size_t)r * P + cc] = o;
                } else {
                    float2 av = *(const float2*)&accb[(size_t)r * P + col];
                    v0 += b_s[col] + av.x;
                    v1 += b_s[col + 1] + av.y;
                    if (MODE == 2) {
                        float2 xv = *(const float2*)&x[(size_t)r * D + col];
                        v0 = 0.5f * (xv.x + v0);
                        v1 = 0.5f * (xv.y + v1);
                    }
                    float2 o; o.x = v0; o.y = v1;
                    *(float2*)&out[(size_t)r * P + col] = o;
                }
            }
        }
    }
}

// ---------------- launch: fork-join two-stream DAG --------------------------
//  s0: gemm_neigh ---------------------------> gather<0> -> gemm_out<0>
//  s1: CSR build (zero,hist,scan,reorder) ---> gather<1> -> gemm_out<1>
extern "C" void kernel_launch(void* const* d_in, const int* in_sizes, int n_in,
                              void* d_out, int out_size) {
    const float* x_ac        = (const float*)d_in[0];
    const float* x_w         = (const float*)d_in[1];
    const int*   src_tic     = (const int*)d_in[2];
    const int*   dst_tic     = (const int*)d_in[3];
    const float* w_tic       = (const float*)d_in[4];
    const int*   src_rel     = (const int*)d_in[5];
    const int*   dst_rel     = (const int*)d_in[6];
    const float* w_rel       = (const float*)d_in[7];
    const float* W_self_tic  = (const float*)d_in[8];
    const float* W_neigh_tic = (const float*)d_in[9];
    const float* b_tic       = (const float*)d_in[10];
    const float* W_self_rel  = (const float*)d_in[11];
    const float* W_neigh_rel = (const float*)d_in[12];
    const float* b_rel       = (const float*)d_in[13];
    float* out = (float*)d_out;

    static cudaStream_t s1 = nullptr;
    static cudaEvent_t ev0 = nullptr, evC = nullptr, evN = nullptr, evD = nullptr;
    if (s1 == nullptr) {
        cudaStreamCreateWithFlags(&s1, cudaStreamNonBlocking);
        cudaEventCreateWithFlags(&ev0, cudaEventDisableTiming);
        cudaEventCreateWithFlags(&evC, cudaEventDisableTiming);
        cudaEventCreateWithFlags(&evN, cudaEventDisableTiming);
        cudaEventCreateWithFlags(&evD, cudaEventDisableTiming);
    }

    const int GRID_A = (NA + 127) / 128;
    const int GRID_W = (NW + 127) / 128;

    // fork
    cudaEventRecord(ev0, 0);
    cudaStreamWaitEvent(s1, ev0, 0);

    // s0: big GEMM producing h_tic / h_rel
    gemm_mma<128, 0, 2, 4><<<GRID_A, 256>>>(x_ac, W_neigh_tic, W_neigh_rel,
                                            nullptr, nullptr, NA);
    cudaEventRecord(evN, 0);

    // s1: CSR build (independent of h)
    zero_cnt<<<(NA + 255) / 256, 256, 0, s1>>>();
    hist<0><<<(E_TIC + 255) / 256, 256, 0, s1>>>(dst_tic, E_TIC);
    hist<1><<<(E_REL + 255) / 256, 256, 0, s1>>>(dst_rel, E_REL);
    scan1<0><<<NB_TIC, 256, 0, s1>>>();
    scan1<1><<<NB_REL, 256, 0, s1>>>();
    scan2<0><<<1, 128, 0, s1>>>();
    scan2<1><<<1, 128, 0, s1>>>();
    scan3<0><<<NB_TIC, 256, 0, s1>>>();
    scan3<1><<<NB_REL, 256, 0, s1>>>();
    reorder<0><<<(E_TIC + 255) / 256, 256, 0, s1>>>(src_tic, dst_tic, w_tic, E_TIC);
    reorder<1><<<(E_REL + 255) / 256, 256, 0, s1>>>(src_rel, dst_rel, w_rel, E_REL);
    cudaEventRecord(evC, s1);

    // cross dependencies
    cudaStreamWaitEvent(0, evC, 0);   // gather<0> needs CSR
    cudaStreamWaitEvent(s1, evN, 0);  // gather<1> needs h_rel

    gather_rows<0><<<(NA + 7) / 8, 256>>>();
    gather_rows<1><<<(NW + 7) / 8, 256, 0, s1>>>();

    gemm_mma<64, 1, 4, 2><<<GRID_A, 256>>>(x_ac, W_self_tic, nullptr,
                                           b_tic, out, NA);
    gemm_mma<64, 2, 4, 2><<<GRID_W, 256, 0, s1>>>(x_w, W_self_rel, nullptr,
                                                  b_rel, out + (size_t)NA * P, NW);

    // join
    cudaEventRecord(evD, s1);
    cudaStreamWaitEvent(0, evD, 0);
}